// round 1
// baseline (speedup 1.0000x reference)
#include <cuda_runtime.h>
#include <math.h>

// Problem constants (fixed by the reference)
#define BB 2
#define SS 2048
#define EE 1024
#define HH 16
#define DH 64
#define M_TOK (BB * SS)        // 4096 tokens
#define N_QKV (3 * EE)         // 3072

// ---------------------------------------------------------------------------
// Scratch (no allocations allowed -> __device__ globals)
// ---------------------------------------------------------------------------
__device__ float g_qkv[M_TOK * N_QKV];   // [4096, 3072]  (q|k|v per token)
__device__ float g_ctx[M_TOK * EE];      // [4096, 1024]  attention context

// ---------------------------------------------------------------------------
// Classic SGEMM: C[M,N] = A[M,K] @ B[K,N] + bias[N]
// 128x128 tile, BK=8, 256 threads, 8x8 register tile per thread.
// Requires M%128==0, N%128==0, K%8==0 (true for all our shapes).
// ---------------------------------------------------------------------------
#define BM 128
#define BN 128
#define BK 8
#define TM 8
#define TN 8

__global__ __launch_bounds__(256, 2)
void sgemm_bias_kernel(const float* __restrict__ A,
                       const float* __restrict__ B,
                       const float* __restrict__ bias,
                       float* __restrict__ C,
                       int M, int N, int K)
{
    __shared__ float As[BK][BM];   // transposed A tile
    __shared__ float Bs[BK][BN];

    const int tid  = threadIdx.x;
    const int tx   = tid % (BN / TN);   // 0..15 -> col group
    const int ty   = tid / (BN / TN);   // 0..15 -> row group
    const int row0 = blockIdx.y * BM;
    const int col0 = blockIdx.x * BN;

    // load indices
    const int arow  = tid >> 1;          // 0..127
    const int acol4 = (tid & 1) * 4;     // 0 or 4
    const int brow  = tid >> 5;          // 0..7
    const int bcol4 = (tid & 31) * 4;    // 0..124

    float acc[TM][TN];
#pragma unroll
    for (int i = 0; i < TM; i++)
#pragma unroll
        for (int j = 0; j < TN; j++) acc[i][j] = 0.0f;

    for (int k0 = 0; k0 < K; k0 += BK) {
        // load A tile (128x8), store transposed
        float4 a = *(const float4*)&A[(size_t)(row0 + arow) * K + k0 + acol4];
        As[acol4 + 0][arow] = a.x;
        As[acol4 + 1][arow] = a.y;
        As[acol4 + 2][arow] = a.z;
        As[acol4 + 3][arow] = a.w;
        // load B tile (8x128)
        float4 b = *(const float4*)&B[(size_t)(k0 + brow) * N + col0 + bcol4];
        *(float4*)&Bs[brow][bcol4] = b;
        __syncthreads();

#pragma unroll
        for (int k = 0; k < BK; k++) {
            float ra[TM], rb[TN];
            const float4* pA = (const float4*)&As[k][ty * TM];
            const float4* pB = (const float4*)&Bs[k][tx * TN];
            float4 a0 = pA[0], a1 = pA[1];
            float4 b0 = pB[0], b1 = pB[1];
            ra[0]=a0.x; ra[1]=a0.y; ra[2]=a0.z; ra[3]=a0.w;
            ra[4]=a1.x; ra[5]=a1.y; ra[6]=a1.z; ra[7]=a1.w;
            rb[0]=b0.x; rb[1]=b0.y; rb[2]=b0.z; rb[3]=b0.w;
            rb[4]=b1.x; rb[5]=b1.y; rb[6]=b1.z; rb[7]=b1.w;
#pragma unroll
            for (int i = 0; i < TM; i++)
#pragma unroll
                for (int j = 0; j < TN; j++)
                    acc[i][j] = fmaf(ra[i], rb[j], acc[i][j]);
        }
        __syncthreads();
    }

    // epilogue: add bias, store
#pragma unroll
    for (int i = 0; i < TM; i++) {
        const int r = row0 + ty * TM + i;
#pragma unroll
        for (int j = 0; j < TN; j++) {
            const int c = col0 + tx * TN + j;
            C[(size_t)r * N + c] = acc[i][j] + bias[c];
        }
    }
}

// ---------------------------------------------------------------------------
// KV cache copy: cache_key = qkv[:, E:2E], cache_value = qkv[:, 2E:3E]
// ---------------------------------------------------------------------------
__global__ void kv_copy_kernel(const float* __restrict__ qkv,
                               float* __restrict__ out_key,
                               float* __restrict__ out_val)
{
    int i4 = blockIdx.x * blockDim.x + threadIdx.x;     // float4 index
    const int total4 = M_TOK * EE / 4;
    if (i4 >= total4) return;
    int i   = i4 * 4;
    int tok = i / EE;
    int j   = i % EE;
    const float4* src = (const float4*)&qkv[(size_t)tok * N_QKV + j];
    *(float4*)&out_key[i] = src[EE / 4];        // offset +E floats = +256 float4
    *(float4*)&out_val[i] = src[2 * EE / 4];    // offset +2E
}

// ---------------------------------------------------------------------------
// Flash attention, fp32, causal + additive bias.
// Tile: 64 q-rows x 64 k-cols, D=64. 256 threads, 4x4 micro-tile per thread.
// Shared: Qs[64][65], Ks[64][65] (reused as P), Vs[64][65]  = 49920 B dynamic.
// ---------------------------------------------------------------------------
#define BQT 64
#define BKT 64
#define PAD 65

__global__ __launch_bounds__(256)
void flash_attn_kernel(const float* __restrict__ qkv,
                       const float* __restrict__ bias,
                       float* __restrict__ ctx)
{
    extern __shared__ float sm[];
    float* Qs = sm;                  // [64][65]
    float* Ks = sm + BQT * PAD;      // [64][65] (reused as P)
    float* Vs = sm + 2 * BQT * PAD;  // [64][65]

    const int qb  = blockIdx.x;      // q tile index (0..31)
    const int h   = blockIdx.y;      // head
    const int b   = blockIdx.z;      // batch
    const int tid = threadIdx.x;
    const int tq  = tid >> 4;        // 0..15 -> q rows tq*4 .. tq*4+3
    const int tk  = tid & 15;        // 0..15 -> cols tk + 16*j

    const int base = b * SS * N_QKV; // fits int (12.6M)
    const float scale = 0.125f;      // 1/sqrt(64)

    // load Q tile (scaled)
    for (int i = tid; i < BQT * DH; i += 256) {
        int r = i >> 6, c = i & 63;
        Qs[r * PAD + c] = qkv[base + (qb * BQT + r) * N_QKV + h * DH + c] * scale;
    }

    float m_i[4], l_i[4], acc[4][4];
#pragma unroll
    for (int i = 0; i < 4; i++) {
        m_i[i] = -1e30f;
        l_i[i] = 0.0f;
#pragma unroll
        for (int j = 0; j < 4; j++) acc[i][j] = 0.0f;
    }

    const int qrow0 = qb * BQT + tq * 4;

    for (int kb = 0; kb <= qb; kb++) {
        __syncthreads();   // previous iteration done reading Ks/Vs (also covers Qs first use)
        // load K,V tiles
        for (int i = tid; i < BKT * DH; i += 256) {
            int r = i >> 6, c = i & 63;
            int g = base + (kb * BKT + r) * N_QKV + h * DH + c;
            Ks[r * PAD + c] = qkv[g + EE];
            Vs[r * PAD + c] = qkv[g + 2 * EE];
        }
        __syncthreads();

        // scores: s[i][j] = sum_d Q[tq*4+i][d] * K[tk+16j][d]
        float s[4][4];
#pragma unroll
        for (int i = 0; i < 4; i++)
#pragma unroll
            for (int j = 0; j < 4; j++) s[i][j] = 0.0f;

#pragma unroll 4
        for (int d = 0; d < DH; d++) {
            float qv[4], kv[4];
#pragma unroll
            for (int i = 0; i < 4; i++) qv[i] = Qs[(tq * 4 + i) * PAD + d];
#pragma unroll
            for (int j = 0; j < 4; j++) kv[j] = Ks[(tk + 16 * j) * PAD + d];
#pragma unroll
            for (int i = 0; i < 4; i++)
#pragma unroll
                for (int j = 0; j < 4; j++)
                    s[i][j] = fmaf(qv[i], kv[j], s[i][j]);
        }

        // bias + causal mask
        const int kcol0 = kb * BKT + tk;
#pragma unroll
        for (int i = 0; i < 4; i++) {
            const int qg = qrow0 + i;
#pragma unroll
            for (int j = 0; j < 4; j++) {
                const int kg = kcol0 + 16 * j;
                float v = s[i][j] + __ldg(&bias[(size_t)qg * SS + kg]);
                s[i][j] = (kg <= qg) ? v : -1e9f;
            }
        }

        // online softmax update (reduce across the 16 lanes sharing tq)
#pragma unroll
        for (int i = 0; i < 4; i++) {
            float mx = fmaxf(fmaxf(s[i][0], s[i][1]), fmaxf(s[i][2], s[i][3]));
#pragma unroll
            for (int o = 1; o < 16; o <<= 1)
                mx = fmaxf(mx, __shfl_xor_sync(0xffffffffu, mx, o));
            float mnew = fmaxf(m_i[i], mx);
            float corr = __expf(m_i[i] - mnew);
            m_i[i] = mnew;
            float rs = 0.0f;
#pragma unroll
            for (int j = 0; j < 4; j++) {
                float p = __expf(s[i][j] - mnew);
                s[i][j] = p;
                rs += p;
            }
#pragma unroll
            for (int o = 1; o < 16; o <<= 1)
                rs += __shfl_xor_sync(0xffffffffu, rs, o);
            l_i[i] = l_i[i] * corr + rs;
#pragma unroll
            for (int j = 0; j < 4; j++) acc[i][j] *= corr;
        }

        __syncthreads();   // everyone done reading Ks
        // write P into Ks buffer
#pragma unroll
        for (int i = 0; i < 4; i++)
#pragma unroll
            for (int j = 0; j < 4; j++)
                Ks[(tq * 4 + i) * PAD + tk + 16 * j] = s[i][j];
        __syncthreads();

        // acc += P @ V   (output d-cols: tk + 16*j)
#pragma unroll 4
        for (int k = 0; k < BKT; k++) {
            float pv[4], vv[4];
#pragma unroll
            for (int i = 0; i < 4; i++) pv[i] = Ks[(tq * 4 + i) * PAD + k];
#pragma unroll
            for (int j = 0; j < 4; j++) vv[j] = Vs[k * PAD + tk + 16 * j];
#pragma unroll
            for (int i = 0; i < 4; i++)
#pragma unroll
                for (int j = 0; j < 4; j++)
                    acc[i][j] = fmaf(pv[i], vv[j], acc[i][j]);
        }
    }

    // write ctx[b, q, h, d]
#pragma unroll
    for (int i = 0; i < 4; i++) {
        const float inv_l = 1.0f / l_i[i];
        const int tokrow = b * SS + qrow0 + i;
#pragma unroll
        for (int j = 0; j < 4; j++)
            ctx[(size_t)tokrow * EE + h * DH + tk + 16 * j] = acc[i][j] * inv_l;
    }
}

// ---------------------------------------------------------------------------
// kernel_launch
// Inputs (metadata order): hidden_states, attn_bias, Wqkv, bqkv, Wproj, bproj
// Output: [out (B*S*E) | cache_key (B*S*E) | cache_value (B*S*E)]
// ---------------------------------------------------------------------------
extern "C" void kernel_launch(void* const* d_in, const int* in_sizes, int n_in,
                              void* d_out, int out_size)
{
    const float* hidden = (const float*)d_in[0];
    const float* bias   = (const float*)d_in[1];
    const float* Wqkv   = (const float*)d_in[2];
    const float* bqkv   = (const float*)d_in[3];
    const float* Wproj  = (const float*)d_in[4];
    const float* bproj  = (const float*)d_in[5];
    float* out = (float*)d_out;

    float* qkv;
    float* ctx;
    cudaGetSymbolAddress((void**)&qkv, g_qkv);
    cudaGetSymbolAddress((void**)&ctx, g_ctx);

    float* out_attn = out;                       // [4096, 1024]
    float* out_key  = out + (size_t)M_TOK * EE;  // [4096, 1024]
    float* out_val  = out + (size_t)2 * M_TOK * EE;

    // allow > 48KB dynamic smem for attention
    static const int attn_smem = 3 * BQT * PAD * 4;  // 49920 bytes
    cudaFuncSetAttribute(flash_attn_kernel,
                         cudaFuncAttributeMaxDynamicSharedMemorySize, attn_smem);

    // 1) QKV = hidden @ Wqkv + bqkv        [4096 x 3072]
    {
        dim3 grid(N_QKV / BN, M_TOK / BM);
        sgemm_bias_kernel<<<grid, 256>>>(hidden, Wqkv, bqkv, qkv,
                                         M_TOK, N_QKV, EE);
    }

    // 2) KV caches
    {
        int total4 = M_TOK * EE / 4;
        kv_copy_kernel<<<(total4 + 255) / 256, 256>>>(qkv, out_key, out_val);
    }

    // 3) Flash attention -> ctx
    {
        dim3 grid(SS / BQT, HH, BB);
        flash_attn_kernel<<<grid, 256, attn_smem>>>(qkv, bias, ctx);
    }

    // 4) out = ctx @ Wproj + bproj         [4096 x 1024]
    {
        dim3 grid(EE / BN, M_TOK / BM);
        sgemm_bias_kernel<<<grid, 256>>>(ctx, Wproj, bproj, out_attn,
                                         M_TOK, EE, EE);
    }
}

// round 2
// speedup vs baseline: 2.9815x; 2.9815x over previous
#include <cuda_runtime.h>
#include <math.h>

// Problem constants
#define BB 2
#define SS 2048
#define EE 1024
#define HH 16
#define DH 64
#define M_TOK (BB * SS)        // 4096
#define N_QKV (3 * EE)         // 3072

// Scratch (__device__ globals; no allocations allowed)
__device__ float g_qkv[M_TOK * N_QKV];
__device__ float g_ctx[M_TOK * EE];

// ---------------------------------------------------------------------------
// helpers
// ---------------------------------------------------------------------------
__device__ __forceinline__ unsigned f2tf(float x) {
    unsigned r;
    asm("cvt.rna.tf32.f32 %0, %1;" : "=r"(r) : "f"(x));
    return r;
}

__device__ __forceinline__ void mma_tf32(float c[4], const unsigned a[4], const unsigned b[2]) {
    asm volatile(
        "mma.sync.aligned.m16n8k8.row.col.f32.tf32.tf32.f32 "
        "{%0,%1,%2,%3}, {%4,%5,%6,%7}, {%8,%9}, {%0,%1,%2,%3};"
        : "+f"(c[0]), "+f"(c[1]), "+f"(c[2]), "+f"(c[3])
        : "r"(a[0]), "r"(a[1]), "r"(a[2]), "r"(a[3]), "r"(b[0]), "r"(b[1]));
}

// ---------------------------------------------------------------------------
// TF32 GEMM: C[M,N] = A[M,K] @ B[K,N] + bias[N]
// 128x128 tile, BK=16, 256 threads (8 warps, warp tile 32x64)
// ---------------------------------------------------------------------------
#define GBM 128
#define GBN 128
#define GBK 16
#define GAS (GBK + 4)    // 20: conflict-free A frag reads
#define GBS (GBN + 8)    // 136: conflict-free B frag reads

__global__ __launch_bounds__(256)
void gemm_tf32_kernel(const float* __restrict__ A,
                      const float* __restrict__ B,
                      const float* __restrict__ bias,
                      float* __restrict__ C,
                      int M, int N, int K)
{
    __shared__ float As[GBM * GAS];
    __shared__ float Bs[GBK * GBS];

    const int tid  = threadIdx.x;
    const int warp = tid >> 5;
    const int lane = tid & 31;
    const int g    = lane >> 2;     // 0..7
    const int tg   = lane & 3;      // 0..3
    const int row0 = blockIdx.y * GBM;
    const int col0 = blockIdx.x * GBN;
    const int wm   = (warp >> 1) * 32;
    const int wn   = (warp & 1) * 64;

    // Global load mapping: A tile 128x16 -> 512 f4; B tile 16x128 -> 512 f4
    const int a_r0 = tid >> 2, a_c4 = (tid & 3) * 4;          // + row 64
    const int b_r0 = tid >> 5, b_c4 = (tid & 31) * 4;         // + row 8

    float4 pa0, pa1, pb0, pb1;
    // preload tile 0
    pa0 = *(const float4*)&A[(size_t)(row0 + a_r0) * K + a_c4];
    pa1 = *(const float4*)&A[(size_t)(row0 + a_r0 + 64) * K + a_c4];
    pb0 = *(const float4*)&B[(size_t)(b_r0) * N + col0 + b_c4];
    pb1 = *(const float4*)&B[(size_t)(b_r0 + 8) * N + col0 + b_c4];

    float acc[2][8][4];
#pragma unroll
    for (int mt = 0; mt < 2; mt++)
#pragma unroll
        for (int nt = 0; nt < 8; nt++)
#pragma unroll
            for (int i = 0; i < 4; i++) acc[mt][nt][i] = 0.0f;

    const int ksteps = K / GBK;
    for (int kt = 0; kt < ksteps; kt++) {
        // store staged regs (convert to tf32 bit patterns)
        {
            unsigned* sa = (unsigned*)As;
            unsigned* sb = (unsigned*)Bs;
            uint4 ua0 = make_uint4(f2tf(pa0.x), f2tf(pa0.y), f2tf(pa0.z), f2tf(pa0.w));
            uint4 ua1 = make_uint4(f2tf(pa1.x), f2tf(pa1.y), f2tf(pa1.z), f2tf(pa1.w));
            uint4 ub0 = make_uint4(f2tf(pb0.x), f2tf(pb0.y), f2tf(pb0.z), f2tf(pb0.w));
            uint4 ub1 = make_uint4(f2tf(pb1.x), f2tf(pb1.y), f2tf(pb1.z), f2tf(pb1.w));
            *(uint4*)&sa[a_r0 * GAS + a_c4]        = ua0;
            *(uint4*)&sa[(a_r0 + 64) * GAS + a_c4] = ua1;
            *(uint4*)&sb[b_r0 * GBS + b_c4]        = ub0;
            *(uint4*)&sb[(b_r0 + 8) * GBS + b_c4]  = ub1;
        }
        __syncthreads();

        // prefetch next tile
        if (kt + 1 < ksteps) {
            const int k0 = (kt + 1) * GBK;
            pa0 = *(const float4*)&A[(size_t)(row0 + a_r0) * K + k0 + a_c4];
            pa1 = *(const float4*)&A[(size_t)(row0 + a_r0 + 64) * K + k0 + a_c4];
            pb0 = *(const float4*)&B[(size_t)(k0 + b_r0) * N + col0 + b_c4];
            pb1 = *(const float4*)&B[(size_t)(k0 + b_r0 + 8) * N + col0 + b_c4];
        }

        const unsigned* sa = (const unsigned*)As;
        const unsigned* sb = (const unsigned*)Bs;
#pragma unroll
        for (int ks = 0; ks < 2; ks++) {
            unsigned af[2][4];
#pragma unroll
            for (int mt = 0; mt < 2; mt++) {
                const int r = wm + mt * 16 + g;
                af[mt][0] = sa[r * GAS + ks * 8 + tg];
                af[mt][1] = sa[(r + 8) * GAS + ks * 8 + tg];
                af[mt][2] = sa[r * GAS + ks * 8 + tg + 4];
                af[mt][3] = sa[(r + 8) * GAS + ks * 8 + tg + 4];
            }
#pragma unroll
            for (int nt = 0; nt < 8; nt++) {
                unsigned bf[2];
                bf[0] = sb[(ks * 8 + tg) * GBS + wn + nt * 8 + g];
                bf[1] = sb[(ks * 8 + tg + 4) * GBS + wn + nt * 8 + g];
#pragma unroll
                for (int mt = 0; mt < 2; mt++)
                    mma_tf32(acc[mt][nt], af[mt], bf);
            }
        }
        __syncthreads();
    }

    // epilogue
#pragma unroll
    for (int mt = 0; mt < 2; mt++) {
        const int r0 = row0 + wm + mt * 16 + g;
#pragma unroll
        for (int nt = 0; nt < 8; nt++) {
            const int c = col0 + wn + nt * 8 + 2 * tg;
            float2 bz = *(const float2*)&bias[c];
            float2 v0 = make_float2(acc[mt][nt][0] + bz.x, acc[mt][nt][1] + bz.y);
            float2 v1 = make_float2(acc[mt][nt][2] + bz.x, acc[mt][nt][3] + bz.y);
            *(float2*)&C[(size_t)r0 * N + c]       = v0;
            *(float2*)&C[(size_t)(r0 + 8) * N + c] = v1;
        }
    }
}

// ---------------------------------------------------------------------------
// KV cache copy
// ---------------------------------------------------------------------------
__global__ void kv_copy_kernel(const float* __restrict__ qkv,
                               float* __restrict__ out_key,
                               float* __restrict__ out_val)
{
    int i4 = blockIdx.x * blockDim.x + threadIdx.x;
    const int total4 = M_TOK * EE / 4;
    if (i4 >= total4) return;
    int i   = i4 * 4;
    int tok = i / EE;
    int j   = i % EE;
    const float4* src = (const float4*)&qkv[(size_t)tok * N_QKV + j];
    *(float4*)&out_key[i] = src[EE / 4];
    *(float4*)&out_val[i] = src[2 * EE / 4];
}

// ---------------------------------------------------------------------------
// Flash attention with mma.sync tf32.
// Block: 128 threads (4 warps), tile 64 q-rows; each warp owns 16 q-rows.
// ---------------------------------------------------------------------------
#define QS_STR 68
#define KS_STR 68
#define VS_STR 72
#define PS_STR 68
#define SM_Q 0
#define SM_K (SM_Q + 64 * QS_STR)
#define SM_V (SM_K + 64 * KS_STR)
#define SM_P (SM_V + 64 * VS_STR)
#define ATTN_SMEM_FLOATS (SM_P + 64 * PS_STR)

__global__ __launch_bounds__(128)
void flash_attn_tf32_kernel(const float* __restrict__ qkv,
                            const float* __restrict__ bias,
                            float* __restrict__ ctx)
{
    extern __shared__ float sm[];
    unsigned* smu = (unsigned*)sm;

    const int qb   = blockIdx.x;
    const int h    = blockIdx.y;
    const int b    = blockIdx.z;
    const int tid  = threadIdx.x;
    const int warp = tid >> 5;
    const int lane = tid & 31;
    const int g    = lane >> 2;
    const int tg   = lane & 3;
    const int w16  = warp * 16;

    const int base = b * SS * N_QKV;
    const float scale = 0.125f;

    // stage Q (scaled + tf32)
#pragma unroll
    for (int i = 0; i < 8; i++) {
        int f = tid + i * 128;              // f4 index over 64x16
        int r = f >> 4, c4 = (f & 15) * 4;
        float4 q = *(const float4*)&qkv[base + (qb * 64 + r) * N_QKV + h * DH + c4];
        uint4 u = make_uint4(f2tf(q.x * scale), f2tf(q.y * scale),
                             f2tf(q.z * scale), f2tf(q.w * scale));
        *(uint4*)&smu[SM_Q + r * QS_STR + c4] = u;
    }
    __syncthreads();

    // Q fragments resident in registers: 8 k-steps x 4 regs
    unsigned qa[8][4];
#pragma unroll
    for (int ks = 0; ks < 8; ks++) {
        const int r = w16 + g;
        qa[ks][0] = smu[SM_Q + r * QS_STR + ks * 8 + tg];
        qa[ks][1] = smu[SM_Q + (r + 8) * QS_STR + ks * 8 + tg];
        qa[ks][2] = smu[SM_Q + r * QS_STR + ks * 8 + tg + 4];
        qa[ks][3] = smu[SM_Q + (r + 8) * QS_STR + ks * 8 + tg + 4];
    }

    float m0 = -1e30f, m1 = -1e30f, l0 = 0.0f, l1 = 0.0f;
    float out[8][4];
#pragma unroll
    for (int nt = 0; nt < 8; nt++)
#pragma unroll
        for (int i = 0; i < 4; i++) out[nt][i] = 0.0f;

    const int qg0 = qb * 64 + w16 + g;
    const int qg1 = qg0 + 8;

    for (int kb = 0; kb <= qb; kb++) {
        __syncthreads();   // prev iter done reading K/V
        // stage K and V tiles (tf32)
#pragma unroll
        for (int i = 0; i < 8; i++) {
            int f = tid + i * 128;
            int r = f >> 4, c4 = (f & 15) * 4;
            int gidx = base + (kb * 64 + r) * N_QKV + h * DH + c4;
            float4 k = *(const float4*)&qkv[gidx + EE];
            float4 v = *(const float4*)&qkv[gidx + 2 * EE];
            *(uint4*)&smu[SM_K + r * KS_STR + c4] =
                make_uint4(f2tf(k.x), f2tf(k.y), f2tf(k.z), f2tf(k.w));
            *(uint4*)&smu[SM_V + r * VS_STR + c4] =
                make_uint4(f2tf(v.x), f2tf(v.y), f2tf(v.z), f2tf(v.w));
        }
        __syncthreads();

        // S = Q K^T  (16x64 per warp)
        float s[8][4];
#pragma unroll
        for (int nt = 0; nt < 8; nt++) {
#pragma unroll
            for (int i = 0; i < 4; i++) s[nt][i] = 0.0f;
#pragma unroll
            for (int ks = 0; ks < 8; ks++) {
                unsigned bf[2];
                bf[0] = smu[SM_K + (nt * 8 + g) * KS_STR + ks * 8 + tg];
                bf[1] = smu[SM_K + (nt * 8 + g) * KS_STR + ks * 8 + tg + 4];
                mma_tf32(s[nt], qa[ks], bf);
            }
        }

        // bias + causal mask
#pragma unroll
        for (int nt = 0; nt < 8; nt++) {
            const int kg = kb * 64 + nt * 8 + 2 * tg;
            float2 bz0 = *(const float2*)&bias[(size_t)qg0 * SS + kg];
            float2 bz1 = *(const float2*)&bias[(size_t)qg1 * SS + kg];
            s[nt][0] += bz0.x; s[nt][1] += bz0.y;
            s[nt][2] += bz1.x; s[nt][3] += bz1.y;
            if (kb == qb) {
                if (kg     > qg0) s[nt][0] = -1e9f;
                if (kg + 1 > qg0) s[nt][1] = -1e9f;
                if (kg     > qg1) s[nt][2] = -1e9f;
                if (kg + 1 > qg1) s[nt][3] = -1e9f;
            }
        }

        // online softmax (rows g and g+8; 4 lanes per row via tg quad)
        float mx0 = -1e30f, mx1 = -1e30f;
#pragma unroll
        for (int nt = 0; nt < 8; nt++) {
            mx0 = fmaxf(mx0, fmaxf(s[nt][0], s[nt][1]));
            mx1 = fmaxf(mx1, fmaxf(s[nt][2], s[nt][3]));
        }
        mx0 = fmaxf(mx0, __shfl_xor_sync(0xffffffffu, mx0, 1));
        mx0 = fmaxf(mx0, __shfl_xor_sync(0xffffffffu, mx0, 2));
        mx1 = fmaxf(mx1, __shfl_xor_sync(0xffffffffu, mx1, 1));
        mx1 = fmaxf(mx1, __shfl_xor_sync(0xffffffffu, mx1, 2));
        float mn0 = fmaxf(m0, mx0), mn1 = fmaxf(m1, mx1);
        float c0 = __expf(m0 - mn0), c1 = __expf(m1 - mn1);
        m0 = mn0; m1 = mn1;

        float rs0 = 0.0f, rs1 = 0.0f;
#pragma unroll
        for (int nt = 0; nt < 8; nt++) {
            s[nt][0] = __expf(s[nt][0] - mn0);
            s[nt][1] = __expf(s[nt][1] - mn0);
            s[nt][2] = __expf(s[nt][2] - mn1);
            s[nt][3] = __expf(s[nt][3] - mn1);
            rs0 += s[nt][0] + s[nt][1];
            rs1 += s[nt][2] + s[nt][3];
        }
        rs0 += __shfl_xor_sync(0xffffffffu, rs0, 1);
        rs0 += __shfl_xor_sync(0xffffffffu, rs0, 2);
        rs1 += __shfl_xor_sync(0xffffffffu, rs1, 1);
        rs1 += __shfl_xor_sync(0xffffffffu, rs1, 2);
        l0 = l0 * c0 + rs0;
        l1 = l1 * c1 + rs1;
#pragma unroll
        for (int nt = 0; nt < 8; nt++) {
            out[nt][0] *= c0; out[nt][1] *= c0;
            out[nt][2] *= c1; out[nt][3] *= c1;
        }

        // P -> smem (per-warp region, tf32)
#pragma unroll
        for (int nt = 0; nt < 8; nt++) {
            uint2 p0 = make_uint2(f2tf(s[nt][0]), f2tf(s[nt][1]));
            uint2 p1 = make_uint2(f2tf(s[nt][2]), f2tf(s[nt][3]));
            *(uint2*)&smu[SM_P + (w16 + g) * PS_STR + nt * 8 + 2 * tg]     = p0;
            *(uint2*)&smu[SM_P + (w16 + g + 8) * PS_STR + nt * 8 + 2 * tg] = p1;
        }
        __syncwarp();

        // out += P V
#pragma unroll
        for (int ks = 0; ks < 8; ks++) {
            unsigned pa[4];
            pa[0] = smu[SM_P + (w16 + g) * PS_STR + ks * 8 + tg];
            pa[1] = smu[SM_P + (w16 + g + 8) * PS_STR + ks * 8 + tg];
            pa[2] = smu[SM_P + (w16 + g) * PS_STR + ks * 8 + tg + 4];
            pa[3] = smu[SM_P + (w16 + g + 8) * PS_STR + ks * 8 + tg + 4];
#pragma unroll
            for (int nt = 0; nt < 8; nt++) {
                unsigned vf[2];
                vf[0] = smu[SM_V + (ks * 8 + tg) * VS_STR + nt * 8 + g];
                vf[1] = smu[SM_V + (ks * 8 + tg + 4) * VS_STR + nt * 8 + g];
                mma_tf32(out[nt], pa, vf);
            }
        }
    }

    // write ctx
    const float il0 = 1.0f / l0, il1 = 1.0f / l1;
    const int tok0 = b * SS + qb * 64 + w16 + g;
#pragma unroll
    for (int nt = 0; nt < 8; nt++) {
        const int c = h * DH + nt * 8 + 2 * tg;
        float2 v0 = make_float2(out[nt][0] * il0, out[nt][1] * il0);
        float2 v1 = make_float2(out[nt][2] * il1, out[nt][3] * il1);
        *(float2*)&ctx[(size_t)tok0 * EE + c]       = v0;
        *(float2*)&ctx[(size_t)(tok0 + 8) * EE + c] = v1;
    }
}

// ---------------------------------------------------------------------------
// kernel_launch
// ---------------------------------------------------------------------------
extern "C" void kernel_launch(void* const* d_in, const int* in_sizes, int n_in,
                              void* d_out, int out_size)
{
    const float* hidden = (const float*)d_in[0];
    const float* bias   = (const float*)d_in[1];
    const float* Wqkv   = (const float*)d_in[2];
    const float* bqkv   = (const float*)d_in[3];
    const float* Wproj  = (const float*)d_in[4];
    const float* bproj  = (const float*)d_in[5];
    float* out = (float*)d_out;

    float* qkv;
    float* ctx;
    cudaGetSymbolAddress((void**)&qkv, g_qkv);
    cudaGetSymbolAddress((void**)&ctx, g_ctx);

    float* out_attn = out;
    float* out_key  = out + (size_t)M_TOK * EE;
    float* out_val  = out + (size_t)2 * M_TOK * EE;

    static const int attn_smem = ATTN_SMEM_FLOATS * 4;   // ~70.7 KB
    cudaFuncSetAttribute(flash_attn_tf32_kernel,
                         cudaFuncAttributeMaxDynamicSharedMemorySize, attn_smem);

    // 1) QKV
    {
        dim3 grid(N_QKV / GBN, M_TOK / GBM);
        gemm_tf32_kernel<<<grid, 256>>>(hidden, Wqkv, bqkv, qkv, M_TOK, N_QKV, EE);
    }
    // 2) KV cache
    {
        int total4 = M_TOK * EE / 4;
        kv_copy_kernel<<<(total4 + 255) / 256, 256>>>(qkv, out_key, out_val);
    }
    // 3) attention
    {
        dim3 grid(SS / 64, HH, BB);
        flash_attn_tf32_kernel<<<grid, 128, attn_smem>>>(qkv, bias, ctx);
    }
    // 4) projection
    {
        dim3 grid(EE / GBN, M_TOK / GBM);
        gemm_tf32_kernel<<<grid, 256>>>(ctx, Wproj, bproj, out_attn, M_TOK, EE, EE);
    }
}